// round 1
// baseline (speedup 1.0000x reference)
#include <cuda_runtime.h>

// ---------------------------------------------------------------------------
// BayesianKAN_ECG: pool(10) -> norm(100,ddof1) -> RBF(16)xGEMM(1600x64) -> tanh
//                  -> norm(64,ddof1) -> RBF(16)xGEMM(1024x5)
// Round 0: fused fp32 kernel, f32x2-packed GEMM1 (2 rows per 64-bit FMA).
// ---------------------------------------------------------------------------

#define SEQ     1000
#define IND     100
#define POOLN   10
#define HID     64
#define OUTD    5
#define NB      16
#define BATCH   65536

#define MTILE   128
#define NTHR    256
#define CI      2              // i's per K-chunk
#define KC      (CI * NB)      // 32
#define NCHUNK  (IND / CI)     // 50

#define XN_STRIDE  101
#define HS_STRIDE  68
#define C2S_STRIDE 132         // 132/4 = 33 (odd) -> conflict-free LDS.128 across lanes

// smem layout (floats)
#define OFF_XN   0
#define OFF_BT   (OFF_XN + MTILE * XN_STRIDE)        // 12928
#define OFF_CS   (OFF_BT + KC * MTILE)               // 12928 + 4096 = 17024
#define OFF_C2S  (OFF_CS + KC * HID)                 // 17024 + 2048 = 19072
#define OFF_CTR  (OFF_C2S + HID * C2S_STRIDE)        // 19072 + 8448 = 27520
#define SMEM_F   (OFF_CTR + 16)                      // 27536 floats
#define SMEM_B   (SMEM_F * 4)                        // 110144 bytes

// -0.5/0.36 * log2(e)
#define NEGK2 (-2.0037431123f)

typedef unsigned long long ull;

// device scratch (transposed coefficients, written by prep kernel each launch)
__device__ float g_c1t[IND * NB * HID];   // [i][n][o64]
__device__ float g_c2t[HID * NB * OUTD];  // [i][n][o5]

__device__ __forceinline__ float fexp2(float x) {
    float r;
    asm("ex2.approx.f32 %0, %1;" : "=f"(r) : "f"(x));
    return r;
}
__device__ __forceinline__ void fma2(ull& acc, ull b, ull c) {
    asm("fma.rn.f32x2 %0, %1, %2, %0;" : "+l"(acc) : "l"(b), "l"(c));
}
__device__ __forceinline__ ull dup2(float f) {
    ull r;
    asm("mov.b64 %0, {%1, %1};" : "=l"(r) : "f"(f));
    return r;
}
__device__ __forceinline__ void unpack2(ull v, float& lo, float& hi) {
    asm("mov.b64 {%0, %1}, %2;" : "=f"(lo), "=f"(hi) : "l"(v));
}

// ---------------------------------------------------------------------------
// Prep: transpose c1 [o64][i100][n16] -> g_c1t [i][n][o]
//       transpose c2 [o5][i64][n16]   -> g_c2t [i][n][o]
// ---------------------------------------------------------------------------
__global__ void kan_prep(const float* __restrict__ c1, const float* __restrict__ c2) {
    int idx = blockIdx.x * blockDim.x + threadIdx.x;
    if (idx < IND * NB * HID) {
        int o = idx & 63;
        int rest = idx >> 6;          // i*16+n
        int n = rest & 15;
        int i = rest >> 4;
        g_c1t[idx] = c1[(o * IND + i) * NB + n];
    }
    if (idx < HID * NB * OUTD) {
        int o = idx % OUTD;
        int rest = idx / OUTD;        // i*16+n
        int n = rest & 15;
        int i = rest >> 4;
        g_c2t[idx] = c2[(o * HID + i) * NB + n];
    }
}

// ---------------------------------------------------------------------------
// Main fused kernel: 1 block = 128 rows
// ---------------------------------------------------------------------------
__global__ void __launch_bounds__(NTHR, 2)
kan_main(const float* __restrict__ x, const float* __restrict__ centers,
         float* __restrict__ out) {
    extern __shared__ float smem[];
    float* xn  = smem + OFF_XN;    // [128][101] pooled+normalized (later hs[128][68])
    float* Bt  = smem + OFF_BT;    // [32][128] basis tile (k-major)
    float* cs  = smem + OFF_CS;    // [32][64]  c1t chunk
    float* c2s = smem + OFF_C2S;   // [64][132] padded c2t
    float* ctr = smem + OFF_CTR;   // [16]

    const int t    = threadIdx.x;
    const int w    = t >> 5;
    const int lane = t & 31;
    const int row0 = blockIdx.x * MTILE;

    // ---- phase 0: centers + c2t into smem --------------------------------
    if (t < NB) ctr[t] = centers[t];
    for (int lin = t; lin < HID * NB * OUTD; lin += NTHR) {
        int o = lin % OUTD;
        int rest = lin / OUTD;       // i*16+n
        int i = rest >> 4;
        int n = rest & 15;
        c2s[i * C2S_STRIDE + n * 8 + o] = g_c2t[lin];
    }

    // ---- phase 1: pooling + norm(100, ddof=1) per row (warp per row) -----
    for (int rr = 0; rr < 16; ++rr) {
        int rl = w * 16 + rr;
        const float* xr = x + (size_t)(row0 + rl) * SEQ;
        float v[4];
        float s1 = 0.f, s2 = 0.f;
#pragma unroll
        for (int rep = 0; rep < 4; ++rep) {
            int p = lane + 32 * rep;
            bool act = (rep < 3) || (lane < 4);
            float acc = 0.f;
            if (act) {
                const float2* xp = (const float2*)(xr + p * POOLN);
#pragma unroll
                for (int j = 0; j < 5; ++j) {
                    float2 q = xp[j];
                    acc += q.x + q.y;
                }
            }
            v[rep] = acc * 0.1f;
            if (act) { s1 += v[rep]; s2 += v[rep] * v[rep]; }
        }
#pragma unroll
        for (int off = 16; off; off >>= 1) {
            s1 += __shfl_xor_sync(0xffffffffu, s1, off);
            s2 += __shfl_xor_sync(0xffffffffu, s2, off);
        }
        float mean = s1 * (1.0f / IND);
        float var  = (s2 - (float)IND * mean * mean) * (1.0f / (IND - 1));
        float inv  = 1.0f / (sqrtf(var) + 1e-6f);
#pragma unroll
        for (int rep = 0; rep < 4; ++rep) {
            int p = lane + 32 * rep;
            if ((rep < 3) || (lane < 4))
                xn[rl * XN_STRIDE + p] = (v[rep] - mean) * inv;
        }
    }
    __syncthreads();

    // ---- phase 2: GEMM1 h[128][64] via f32x2 (2 rows per accumulator) ----
    const int r    = t & 127;   // row for basis build
    const int half = t >> 7;    // which i of the chunk
    const int ty   = t >> 4;    // 0..15 : rows 8*ty..8*ty+7
    const int tx   = t & 15;    // 0..15 : outs 4*tx..4*tx+3

    ull acc[4][4];
#pragma unroll
    for (int a = 0; a < 4; ++a)
#pragma unroll
        for (int b = 0; b < 4; ++b) acc[a][b] = 0ull;

    for (int ch = 0; ch < NCHUNK; ++ch) {
        // basis tile: Bt[k][r], k = half*16+n, for i = ch*2+half
        {
            float xv = xn[r * XN_STRIDE + ch * CI + half];
#pragma unroll
            for (int n = 0; n < NB; ++n) {
                float d = xv - ctr[n];
                Bt[(half * NB + n) * MTILE + r] = fexp2(d * d * NEGK2);
            }
        }
        // coefficient chunk: 2048 floats, coalesced float4
        {
            const float4* src = (const float4*)(g_c1t + ch * (KC * HID));
            float4* dst = (float4*)cs;
            dst[t]       = src[t];
            dst[t + 256] = src[t + 256];
        }
        __syncthreads();

#pragma unroll 8
        for (int k = 0; k < KC; ++k) {
            const float* bp = Bt + k * MTILE + 8 * ty;
            ulonglong2 b01 = *(const ulonglong2*)(bp);       // rows 8ty+0/1, +2/3
            ulonglong2 b23 = *(const ulonglong2*)(bp + 4);   // rows 8ty+4/5, +6/7
            float4 c4 = *(const float4*)(cs + k * HID + 4 * tx);
            ull c0 = dup2(c4.x), c1p = dup2(c4.y), c2p = dup2(c4.z), c3p = dup2(c4.w);

            fma2(acc[0][0], b01.x, c0);  fma2(acc[0][1], b01.x, c1p);
            fma2(acc[0][2], b01.x, c2p); fma2(acc[0][3], b01.x, c3p);
            fma2(acc[1][0], b01.y, c0);  fma2(acc[1][1], b01.y, c1p);
            fma2(acc[1][2], b01.y, c2p); fma2(acc[1][3], b01.y, c3p);
            fma2(acc[2][0], b23.x, c0);  fma2(acc[2][1], b23.x, c1p);
            fma2(acc[2][2], b23.x, c2p); fma2(acc[2][3], b23.x, c3p);
            fma2(acc[3][0], b23.y, c0);  fma2(acc[3][1], b23.y, c1p);
            fma2(acc[3][2], b23.y, c2p); fma2(acc[3][3], b23.y, c3p);
        }
        __syncthreads();
    }

    // ---- phase 3: tanh -> hs (reuse xn region, stride 68) ----------------
    float* hs = smem + OFF_XN;   // [128][68]
#pragma unroll
    for (int rp = 0; rp < 4; ++rp) {
        float lo[4], hi[4];
#pragma unroll
        for (int j = 0; j < 4; ++j) unpack2(acc[rp][j], lo[j], hi[j]);
        int r0 = 8 * ty + 2 * rp;
        *(float4*)&hs[r0 * HS_STRIDE + 4 * tx] =
            make_float4(tanhf(lo[0]), tanhf(lo[1]), tanhf(lo[2]), tanhf(lo[3]));
        *(float4*)&hs[(r0 + 1) * HS_STRIDE + 4 * tx] =
            make_float4(tanhf(hi[0]), tanhf(hi[1]), tanhf(hi[2]), tanhf(hi[3]));
    }
    __syncthreads();

    // ---- phase 4: norm(64, ddof=1) + layer2 (warp per row) ---------------
    for (int rr = 0; rr < 16; ++rr) {
        int rl = w * 16 + rr;
        float a = hs[rl * HS_STRIDE + lane];
        float b = hs[rl * HS_STRIDE + 32 + lane];
        float s1 = a + b;
        float s2 = a * a + b * b;
#pragma unroll
        for (int off = 16; off; off >>= 1) {
            s1 += __shfl_xor_sync(0xffffffffu, s1, off);
            s2 += __shfl_xor_sync(0xffffffffu, s2, off);
        }
        float mean = s1 * (1.0f / HID);
        float var  = (s2 - (float)HID * mean * mean) * (1.0f / (HID - 1));
        float inv  = 1.0f / (sqrtf(var) + 1e-6f);
        float h0 = (a - mean) * inv;
        float h1 = (b - mean) * inv;

        float o0 = 0.f, o1 = 0.f, o2 = 0.f, o3 = 0.f, o4 = 0.f;
#pragma unroll
        for (int hsel = 0; hsel < 2; ++hsel) {
            float v = hsel ? h1 : h0;
            const float* crow = c2s + (lane + 32 * hsel) * C2S_STRIDE;
#pragma unroll
            for (int n = 0; n < NB; ++n) {
                float d = v - ctr[n];
                float e = fexp2(d * d * NEGK2);
                float4 c4 = *(const float4*)(crow + n * 8);
                float c5 = crow[n * 8 + 4];
                o0 += e * c4.x; o1 += e * c4.y; o2 += e * c4.z;
                o3 += e * c4.w; o4 += e * c5;
            }
        }
#pragma unroll
        for (int off = 16; off; off >>= 1) {
            o0 += __shfl_xor_sync(0xffffffffu, o0, off);
            o1 += __shfl_xor_sync(0xffffffffu, o1, off);
            o2 += __shfl_xor_sync(0xffffffffu, o2, off);
            o3 += __shfl_xor_sync(0xffffffffu, o3, off);
            o4 += __shfl_xor_sync(0xffffffffu, o4, off);
        }
        if (lane == 0) {
            float* op = out + (size_t)(row0 + rl) * OUTD;
            op[0] = o0; op[1] = o1; op[2] = o2; op[3] = o3; op[4] = o4;
        }
    }
}

// ---------------------------------------------------------------------------
extern "C" void kernel_launch(void* const* d_in, const int* in_sizes, int n_in,
                              void* d_out, int out_size) {
    (void)in_sizes; (void)n_in; (void)out_size;
    const float* x       = (const float*)d_in[0];
    const float* c1      = (const float*)d_in[1];
    const float* c2      = (const float*)d_in[2];
    const float* centers = (const float*)d_in[3];
    float* out = (float*)d_out;

    // idempotent, not a stream op: safe under graph capture
    cudaFuncSetAttribute(kan_main, cudaFuncAttributeMaxDynamicSharedMemorySize, SMEM_B);

    kan_prep<<<(IND * NB * HID + NTHR - 1) / NTHR, NTHR>>>(c1, c2);
    kan_main<<<BATCH / MTILE, NTHR, SMEM_B>>>(x, centers, out);
}

// round 3
// speedup vs baseline: 2.1816x; 2.1816x over previous
#include <cuda_runtime.h>
#include <cuda_fp16.h>
#include <cstdint>

// ---------------------------------------------------------------------------
// BayesianKAN_ECG round 3: warp-level mma.sync m16n8k16 (HMMA) with hi/lo
// fp16 operand splitting (3 MMAs -> fp32-quality). tcgen05 is not available
// (toolchain targets plain sm_103).
// ---------------------------------------------------------------------------

#define SEQ     1000
#define IND     100
#define POOLN   10
#define HID     64
#define OUTD    5
#define NB      16
#define BATCH   65536

#define MTILE   128
#define NTHR    256

#define NI1     100       // layer-1 i count
#define NI2     64        // layer-2 i count
#define CH1     10        // i's per smem chunk
#define NCH1    (NI1/CH1) // 10

#define XSTR    101       // xn row stride (floats)
#define HST     66        // hs row stride (floats)

// sqrt(0.5/0.36 * log2(e)); basis = ex2(-(x*S - c*S)^2)
#define SCALE   1.4155364f

// smem byte layout
#define SM_CTR   0                       // 16 f32
#define SM_XN    128                     // 128*101*4 = 51712
#define SM_W     (SM_XN + 51712)         // 51840
#define W_BYTES  (CH1 * 2 * 8 * 32 * 8)  // 40960
#define SM_TOTAL (SM_W + W_BYTES)        // 92800

// prep-built fragment-linear coefficient tables (halves)
// layer1: [(i*2+set)*8+nf][lane][4]  (set 0=hi, 1=lo)
__device__ __align__(16) __half g_w1[NI1 * 2 * 8 * 32 * 4];   // 1.6MB
// layer2: [(i*2+set)][lane][4]
__device__ __align__(16) __half g_w2[NI2 * 2 * 32 * 4];       // 32KB

// ---------------------------------------------------------------------------
__device__ __forceinline__ float fexp2(float x) {
    float r; asm("ex2.approx.f32 %0, %1;" : "=f"(r) : "f"(x)); return r;
}
__device__ __forceinline__ uint32_t pack2(__half a, __half b) {
    __half2 h = __halves2half2(a, b);
    return *(uint32_t*)&h;
}
__device__ __forceinline__ void mma16816(float* d, const uint32_t* a,
                                         uint32_t b0, uint32_t b1) {
    asm volatile(
        "mma.sync.aligned.m16n8k16.row.col.f32.f16.f16.f32 "
        "{%0,%1,%2,%3}, {%4,%5,%6,%7}, {%8,%9}, {%0,%1,%2,%3};"
        : "+f"(d[0]), "+f"(d[1]), "+f"(d[2]), "+f"(d[3])
        : "r"(a[0]), "r"(a[1]), "r"(a[2]), "r"(a[3]), "r"(b0), "r"(b1));
}

// Build A fragments (hi + lo residual) for one i: 8 basis values per thread.
// x0/x1 are the two row values (already SCALE'd); cc[4] the lane's centers.
__device__ __forceinline__ void build_a(float x0, float x1, const float* cc,
                                        uint32_t* ah, uint32_t* al) {
    float e[8];
#pragma unroll
    for (int j = 0; j < 4; ++j) {
        float d0 = x0 - cc[j];
        float d1 = x1 - cc[j];
        e[j]     = fexp2(__fmul_rn(d0, -d0));
        e[4 + j] = fexp2(__fmul_rn(d1, -d1));
    }
    __half h[8]; float r[8];
#pragma unroll
    for (int j = 0; j < 8; ++j) {
        h[j] = __float2half_rn(e[j]);
        r[j] = e[j] - __half2float(h[j]);
    }
    // a0: row gid, k lo-pair; a1: row gid+8, k lo-pair; a2/a3: k hi-pair
    ah[0] = pack2(h[0], h[1]);
    ah[1] = pack2(h[4], h[5]);
    ah[2] = pack2(h[2], h[3]);
    ah[3] = pack2(h[6], h[7]);
    al[0] = pack2(__float2half_rn(r[0]), __float2half_rn(r[1]));
    al[1] = pack2(__float2half_rn(r[4]), __float2half_rn(r[5]));
    al[2] = pack2(__float2half_rn(r[2]), __float2half_rn(r[3]));
    al[3] = pack2(__float2half_rn(r[6]), __float2half_rn(r[7]));
}

// ---------------------------------------------------------------------------
// Prep: arrange c1/c2 into per-lane fragment layout, hi/lo fp16 split.
// position idx = (i*8 + nf)*32 + lane  (layer1);  i*32 + lane (layer2)
// ---------------------------------------------------------------------------
__global__ void kan_prep(const float* __restrict__ c1, const float* __restrict__ c2) {
    int idx = blockIdx.x * blockDim.x + threadIdx.x;
    if (idx < NI1 * 8 * 32) {
        int lane = idx & 31, nf = (idx >> 5) & 7, i = idx >> 8;
        int gid = lane >> 2, qid = lane & 3;
        int o = nf * 8 + gid;
        __half hi[4], lo[4];
#pragma unroll
        for (int h = 0; h < 4; ++h) {
            int kl = qid * 2 + (h & 1) + ((h >> 1) * 8);
            float c = c1[(o * IND + i) * NB + kl];
            __half ch = __float2half_rn(c);
            hi[h] = ch;
            lo[h] = __float2half_rn(c - __half2float(ch));
        }
        *(uint2*)&g_w1[(((i * 2 + 0) * 8 + nf) * 32 + lane) * 4] = *(uint2*)hi;
        *(uint2*)&g_w1[(((i * 2 + 1) * 8 + nf) * 32 + lane) * 4] = *(uint2*)lo;
    }
    if (idx < NI2 * 32) {
        int lane = idx & 31, i = idx >> 5;
        int gid = lane >> 2, qid = lane & 3;
        __half hi[4], lo[4];
#pragma unroll
        for (int h = 0; h < 4; ++h) {
            int kl = qid * 2 + (h & 1) + ((h >> 1) * 8);
            float c = (gid < OUTD) ? c2[(gid * HID + i) * NB + kl] : 0.0f;
            __half ch = __float2half_rn(c);
            hi[h] = ch;
            lo[h] = __float2half_rn(c - __half2float(ch));
        }
        *(uint2*)&g_w2[((i * 2 + 0) * 32 + lane) * 4] = *(uint2*)hi;
        *(uint2*)&g_w2[((i * 2 + 1) * 32 + lane) * 4] = *(uint2*)lo;
    }
}

// ---------------------------------------------------------------------------
// Main fused kernel: 1 block = 128 rows, 8 warps (16 rows each)
// ---------------------------------------------------------------------------
__global__ void __launch_bounds__(NTHR, 2)
kan_main(const float* __restrict__ x, const float* __restrict__ centers,
         float* __restrict__ out) {
    extern __shared__ char smc[];
    float* ctr = (float*)(smc + SM_CTR);
    float* xn  = (float*)(smc + SM_XN);
    float* hs  = (float*)(smc + SM_XN);          // overlays xn after layer 1
    const uint2* Wb = (const uint2*)(smc + SM_W);

    const int t    = threadIdx.x;
    const int w    = t >> 5;
    const int lane = t & 31;
    const int gid  = lane >> 2;
    const int qid  = lane & 3;
    const int rw   = w * 16;
    const int row0 = blockIdx.x * MTILE;

    if (t < NB) ctr[t] = centers[t] * SCALE;

    // ---- phase 1: pooling + norm(100, ddof=1), warp per row ---------------
    for (int rr = 0; rr < 16; ++rr) {
        int rl = w * 16 + rr;
        const float* xr = x + (size_t)(row0 + rl) * SEQ;
        float v[4];
        float s1 = 0.f, s2 = 0.f;
#pragma unroll
        for (int rep = 0; rep < 4; ++rep) {
            int p = lane + 32 * rep;
            bool act = (rep < 3) || (lane < 4);
            float acc = 0.f;
            if (act) {
                const float2* xp = (const float2*)(xr + p * POOLN);
#pragma unroll
                for (int j = 0; j < 5; ++j) { float2 q = xp[j]; acc += q.x + q.y; }
            }
            v[rep] = acc * 0.1f;
            if (act) { s1 += v[rep]; s2 += v[rep] * v[rep]; }
        }
#pragma unroll
        for (int off = 16; off; off >>= 1) {
            s1 += __shfl_xor_sync(0xffffffffu, s1, off);
            s2 += __shfl_xor_sync(0xffffffffu, s2, off);
        }
        float mean = s1 * (1.0f / IND);
        float var  = (s2 - (float)IND * mean * mean) * (1.0f / (IND - 1));
        float inv  = SCALE / (sqrtf(var) + 1e-6f);
#pragma unroll
        for (int rep = 0; rep < 4; ++rep) {
            int p = lane + 32 * rep;
            if ((rep < 3) || (lane < 4))
                xn[rl * XSTR + p] = (v[rep] - mean) * inv;
        }
    }

    // lane's 4 centers (fixed by qid)
    float cc[4];
    __syncthreads();
    cc[0] = ctr[qid * 2];     cc[1] = ctr[qid * 2 + 1];
    cc[2] = ctr[qid * 2 + 8]; cc[3] = ctr[qid * 2 + 9];

    const int r0 = rw + gid, r1 = r0 + 8;

    // ---- layer 1: K = 100 i x 16 basis, 8 n-frags, hi/lo split (3 MMAs) ---
    float acc[8][4];
#pragma unroll
    for (int nf = 0; nf < 8; ++nf)
#pragma unroll
        for (int j = 0; j < 4; ++j) acc[nf][j] = 0.f;

    for (int ch = 0; ch < NCH1; ++ch) {
        // stage W chunk (40KB): 10 uint4 per thread
        __syncthreads();
        {
            const uint4* src = (const uint4*)((const char*)g_w1 + ch * W_BYTES);
            uint4* dst = (uint4*)(smc + SM_W);
#pragma unroll
            for (int j = 0; j < 10; ++j) dst[t + j * 256] = src[t + j * 256];
        }
        __syncthreads();

        for (int il = 0; il < CH1; ++il) {
            int i = ch * CH1 + il;
            float x0 = xn[r0 * XSTR + i];
            float x1 = xn[r1 * XSTR + i];
            uint32_t ah[4], al[4];
            build_a(x0, x1, cc, ah, al);
            const uint2* bh = Wb + ((il * 2 + 0) * 8) * 32 + lane;
            const uint2* bl = Wb + ((il * 2 + 1) * 8) * 32 + lane;
#pragma unroll
            for (int nf = 0; nf < 8; ++nf) {
                uint2 vh = bh[nf * 32];
                uint2 vl = bl[nf * 32];
                mma16816(acc[nf], ah, vh.x, vh.y);
                mma16816(acc[nf], ah, vl.x, vl.y);
                mma16816(acc[nf], al, vh.x, vh.y);
            }
        }
    }
    __syncthreads();   // all warps done reading xn before hs overwrite

    // ---- epilogue: tanh + norm(64, ddof=1) via quad reduction -------------
    {
        float s1a = 0.f, s2a = 0.f, s1b = 0.f, s2b = 0.f;
#pragma unroll
        for (int nf = 0; nf < 8; ++nf) {
            acc[nf][0] = tanhf(acc[nf][0]); acc[nf][1] = tanhf(acc[nf][1]);
            acc[nf][2] = tanhf(acc[nf][2]); acc[nf][3] = tanhf(acc[nf][3]);
            s1a += acc[nf][0] + acc[nf][1]; s2a += acc[nf][0] * acc[nf][0] + acc[nf][1] * acc[nf][1];
            s1b += acc[nf][2] + acc[nf][3]; s2b += acc[nf][2] * acc[nf][2] + acc[nf][3] * acc[nf][3];
        }
#pragma unroll
        for (int off = 1; off < 4; off <<= 1) {
            s1a += __shfl_xor_sync(0xffffffffu, s1a, off);
            s2a += __shfl_xor_sync(0xffffffffu, s2a, off);
            s1b += __shfl_xor_sync(0xffffffffu, s1b, off);
            s2b += __shfl_xor_sync(0xffffffffu, s2b, off);
        }
        float ma = s1a * (1.0f / HID);
        float va = (s2a - (float)HID * ma * ma) * (1.0f / (HID - 1));
        float ia = SCALE / (sqrtf(va) + 1e-6f);
        float mb = s1b * (1.0f / HID);
        float vb = (s2b - (float)HID * mb * mb) * (1.0f / (HID - 1));
        float ib = SCALE / (sqrtf(vb) + 1e-6f);
#pragma unroll
        for (int nf = 0; nf < 8; ++nf) {
            int c0 = nf * 8 + qid * 2;
            *(float2*)&hs[r0 * HST + c0] =
                make_float2((acc[nf][0] - ma) * ia, (acc[nf][1] - ma) * ia);
            *(float2*)&hs[r1 * HST + c0] =
                make_float2((acc[nf][2] - mb) * ib, (acc[nf][3] - mb) * ib);
        }
    }
    __syncthreads();

    // stage layer-2 coefficients (32KB resident)
    {
        const uint4* src = (const uint4*)g_w2;
        uint4* dst = (uint4*)(smc + SM_W);
#pragma unroll
        for (int j = 0; j < 8; ++j) dst[t + j * 256] = src[t + j * 256];
    }
    __syncthreads();

    // ---- layer 2: K = 64 i x 16 basis, 1 n-frag ---------------------------
    float acc2[4] = {0.f, 0.f, 0.f, 0.f};
    for (int i = 0; i < NI2; ++i) {
        float x0 = hs[r0 * HST + i];
        float x1 = hs[r1 * HST + i];
        uint32_t ah[4], al[4];
        build_a(x0, x1, cc, ah, al);
        uint2 vh = Wb[(i * 2 + 0) * 32 + lane];
        uint2 vl = Wb[(i * 2 + 1) * 32 + lane];
        mma16816(acc2, ah, vh.x, vh.y);
        mma16816(acc2, ah, vl.x, vl.y);
        mma16816(acc2, al, vh.x, vh.y);
    }

    // ---- output: cols 0..4 of the n-frag ----------------------------------
    {
        float* op0 = out + (size_t)(row0 + r0) * OUTD;
        float* op1 = out + (size_t)(row0 + r1) * OUTD;
        if (qid < 2) {
            op0[qid * 2]     = acc2[0];
            op0[qid * 2 + 1] = acc2[1];
            op1[qid * 2]     = acc2[2];
            op1[qid * 2 + 1] = acc2[3];
        } else if (qid == 2) {
            op0[4] = acc2[0];
            op1[4] = acc2[2];
        }
    }
}

// ---------------------------------------------------------------------------
extern "C" void kernel_launch(void* const* d_in, const int* in_sizes, int n_in,
                              void* d_out, int out_size) {
    (void)in_sizes; (void)n_in; (void)out_size;
    const float* x       = (const float*)d_in[0];
    const float* c1      = (const float*)d_in[1];
    const float* c2      = (const float*)d_in[2];
    const float* centers = (const float*)d_in[3];
    float* out = (float*)d_out;

    cudaFuncSetAttribute(kan_main, cudaFuncAttributeMaxDynamicSharedMemorySize, SM_TOTAL);

    kan_prep<<<(NI1 * 8 * 32 + NTHR - 1) / NTHR, NTHR>>>(c1, c2);
    kan_main<<<BATCH / MTILE, NTHR, SM_TOTAL>>>(x, centers, out);
}

// round 4
// speedup vs baseline: 2.5182x; 1.1543x over previous
#include <cuda_runtime.h>
#include <cuda_fp16.h>
#include <cstdint>

// ---------------------------------------------------------------------------
// BayesianKAN_ECG round 4: HMMA m16n8k16, A split hi/lo via exact mantissa
// mask (2 MMAs), B single fp16 (halves LDS traffic), 3 CTAs/SM.
// ---------------------------------------------------------------------------

#define SEQ     1000
#define IND     100
#define POOLN   10
#define HID     64
#define OUTD    5
#define NB      16
#define BATCH   65536

#define MTILE   128
#define NTHR    256

#define NI1     100
#define NI2     64
#define CH1     10
#define NCH1    (NI1/CH1)

#define XSTR    101
#define HST     66

// sqrt(0.5/0.36 * log2(e)); basis = ex2(-(x*S - c*S)^2)
#define SCALE   1.4155364f

// smem byte layout
#define SM_CTR   0
#define SM_XN    128                     // 128*101*4 = 51712
#define SM_W     (SM_XN + 51712)         // 51840
#define W_BYTES  (CH1 * 8 * 32 * 8)      // 20480 (hi only)
#define SM_TOTAL (SM_W + W_BYTES)        // 72320  -> 3 CTAs/SM

// fragment-linear fp16 coefficient tables (single set)
__device__ __align__(16) __half g_w1[NI1 * 8 * 32 * 4];   // 200KB
__device__ __align__(16) __half g_w2[NI2 * 32 * 4];       // 16KB

// ---------------------------------------------------------------------------
__device__ __forceinline__ float fexp2(float x) {
    float r; asm("ex2.approx.f32 %0, %1;" : "=f"(r) : "f"(x)); return r;
}
// pack {lo half = l, hi half = h} as f16x2 in one cvt
__device__ __forceinline__ uint32_t f16x2(float l, float h) {
    uint32_t r;
    asm("cvt.rn.f16x2.f32 %0, %1, %2;" : "=r"(r) : "f"(h), "f"(l));
    return r;
}
__device__ __forceinline__ void mma16816(float* d, const uint32_t* a,
                                         uint32_t b0, uint32_t b1) {
    asm volatile(
        "mma.sync.aligned.m16n8k16.row.col.f32.f16.f16.f32 "
        "{%0,%1,%2,%3}, {%4,%5,%6,%7}, {%8,%9}, {%0,%1,%2,%3};"
        : "+f"(d[0]), "+f"(d[1]), "+f"(d[2]), "+f"(d[3])
        : "r"(a[0]), "r"(a[1]), "r"(a[2]), "r"(a[3]), "r"(b0), "r"(b1));
}

// Build A fragments: basis values, exact hi/lo split via mantissa mask.
// hi keeps top 10 mantissa bits (fp16-exact for normal range); lo = e - hi.
__device__ __forceinline__ void build_a(float x0, float x1, const float* cc,
                                        uint32_t* ah, uint32_t* al) {
    float e[8];
#pragma unroll
    for (int j = 0; j < 4; ++j) {
        float d0 = x0 - cc[j];
        float d1 = x1 - cc[j];
        e[j]     = fexp2(__fmul_rn(d0, -d0));
        e[4 + j] = fexp2(__fmul_rn(d1, -d1));
    }
    float h[8], l[8];
#pragma unroll
    for (int j = 0; j < 8; ++j) {
        h[j] = __uint_as_float(__float_as_uint(e[j]) & 0xFFFFE000u);
        l[j] = e[j] - h[j];
    }
    ah[0] = f16x2(h[0], h[1]);  ah[1] = f16x2(h[4], h[5]);
    ah[2] = f16x2(h[2], h[3]);  ah[3] = f16x2(h[6], h[7]);
    al[0] = f16x2(l[0], l[1]);  al[1] = f16x2(l[4], l[5]);
    al[2] = f16x2(l[2], l[3]);  al[3] = f16x2(l[6], l[7]);
}

// ---------------------------------------------------------------------------
// Prep: per-lane fragment layout, single fp16 set.
// ---------------------------------------------------------------------------
__global__ void kan_prep(const float* __restrict__ c1, const float* __restrict__ c2) {
    int idx = blockIdx.x * blockDim.x + threadIdx.x;
    if (idx < NI1 * 8 * 32) {
        int lane = idx & 31, nf = (idx >> 5) & 7, i = idx >> 8;
        int gid = lane >> 2, qid = lane & 3;
        int o = nf * 8 + gid;
        __half h[4];
#pragma unroll
        for (int v = 0; v < 4; ++v) {
            int kl = qid * 2 + (v & 1) + ((v >> 1) * 8);
            h[v] = __float2half_rn(c1[(o * IND + i) * NB + kl]);
        }
        *(uint2*)&g_w1[idx * 4] = *(uint2*)h;
    }
    if (idx < NI2 * 32) {
        int lane = idx & 31, i = idx >> 5;
        int gid = lane >> 2, qid = lane & 3;
        __half h[4];
#pragma unroll
        for (int v = 0; v < 4; ++v) {
            int kl = qid * 2 + (v & 1) + ((v >> 1) * 8);
            h[v] = __float2half_rn((gid < OUTD) ? c2[(gid * HID + i) * NB + kl] : 0.0f);
        }
        *(uint2*)&g_w2[idx * 4] = *(uint2*)h;
    }
}

// ---------------------------------------------------------------------------
// Main fused kernel: 1 block = 128 rows, 8 warps (16 rows each)
// ---------------------------------------------------------------------------
__global__ void __launch_bounds__(NTHR, 3)
kan_main(const float* __restrict__ x, const float* __restrict__ centers,
         float* __restrict__ out) {
    extern __shared__ char smc[];
    float* ctr = (float*)(smc + SM_CTR);
    float* xn  = (float*)(smc + SM_XN);
    float* hs  = (float*)(smc + SM_XN);          // overlays xn after layer 1
    const uint2* Wb = (const uint2*)(smc + SM_W);

    const int t    = threadIdx.x;
    const int w    = t >> 5;
    const int lane = t & 31;
    const int gid  = lane >> 2;
    const int qid  = lane & 3;
    const int row0 = blockIdx.x * MTILE;

    if (t < NB) ctr[t] = centers[t] * SCALE;

    // ---- phase 1: pooling + norm(100, ddof=1), warp per row ---------------
    for (int rr = 0; rr < 16; ++rr) {
        int rl = w * 16 + rr;
        const float* xr = x + (size_t)(row0 + rl) * SEQ;
        float v[4];
        float s1 = 0.f, s2 = 0.f;
#pragma unroll
        for (int rep = 0; rep < 4; ++rep) {
            int p = lane + 32 * rep;
            bool act = (rep < 3) || (lane < 4);
            float acc = 0.f;
            if (act) {
                const float2* xp = (const float2*)(xr + p * POOLN);
#pragma unroll
                for (int j = 0; j < 5; ++j) { float2 q = xp[j]; acc += q.x + q.y; }
            }
            v[rep] = acc * 0.1f;
            if (act) { s1 += v[rep]; s2 += v[rep] * v[rep]; }
        }
#pragma unroll
        for (int off = 16; off; off >>= 1) {
            s1 += __shfl_xor_sync(0xffffffffu, s1, off);
            s2 += __shfl_xor_sync(0xffffffffu, s2, off);
        }
        float mean = s1 * (1.0f / IND);
        float var  = (s2 - (float)IND * mean * mean) * (1.0f / (IND - 1));
        float inv  = SCALE / (sqrtf(var) + 1e-6f);
#pragma unroll
        for (int rep = 0; rep < 4; ++rep) {
            int p = lane + 32 * rep;
            if ((rep < 3) || (lane < 4))
                xn[rl * XSTR + p] = (v[rep] - mean) * inv;
        }
    }

    float cc[4];
    __syncthreads();
    cc[0] = ctr[qid * 2];     cc[1] = ctr[qid * 2 + 1];
    cc[2] = ctr[qid * 2 + 8]; cc[3] = ctr[qid * 2 + 9];

    const int r0 = w * 16 + gid, r1 = r0 + 8;

    // ---- layer 1: K = 100 x 16, 8 n-frags, 2 MMAs per (i, nf) -------------
    float acc[8][4];
#pragma unroll
    for (int nf = 0; nf < 8; ++nf)
#pragma unroll
        for (int j = 0; j < 4; ++j) acc[nf][j] = 0.f;

    for (int ch = 0; ch < NCH1; ++ch) {
        __syncthreads();
        {
            const uint4* src = (const uint4*)((const char*)g_w1 + ch * W_BYTES);
            uint4* dst = (uint4*)(smc + SM_W);
#pragma unroll
            for (int j = 0; j < 5; ++j) dst[t + j * 256] = src[t + j * 256];
        }
        __syncthreads();

        for (int il = 0; il < CH1; ++il) {
            int i = ch * CH1 + il;
            float x0 = xn[r0 * XSTR + i];
            float x1 = xn[r1 * XSTR + i];
            uint32_t ah[4], al[4];
            build_a(x0, x1, cc, ah, al);
            const uint2* bp = Wb + il * 256 + lane;
#pragma unroll
            for (int nf = 0; nf < 8; ++nf) {
                uint2 v = bp[nf * 32];
                mma16816(acc[nf], ah, v.x, v.y);
                mma16816(acc[nf], al, v.x, v.y);
            }
        }
    }
    __syncthreads();   // all warps done reading xn before hs overwrite

    // ---- epilogue: tanh + norm(64, ddof=1) via quad reduction -------------
    {
        float s1a = 0.f, s2a = 0.f, s1b = 0.f, s2b = 0.f;
#pragma unroll
        for (int nf = 0; nf < 8; ++nf) {
            acc[nf][0] = tanhf(acc[nf][0]); acc[nf][1] = tanhf(acc[nf][1]);
            acc[nf][2] = tanhf(acc[nf][2]); acc[nf][3] = tanhf(acc[nf][3]);
            s1a += acc[nf][0] + acc[nf][1]; s2a += acc[nf][0] * acc[nf][0] + acc[nf][1] * acc[nf][1];
            s1b += acc[nf][2] + acc[nf][3]; s2b += acc[nf][2] * acc[nf][2] + acc[nf][3] * acc[nf][3];
        }
#pragma unroll
        for (int off = 1; off < 4; off <<= 1) {
            s1a += __shfl_xor_sync(0xffffffffu, s1a, off);
            s2a += __shfl_xor_sync(0xffffffffu, s2a, off);
            s1b += __shfl_xor_sync(0xffffffffu, s1b, off);
            s2b += __shfl_xor_sync(0xffffffffu, s2b, off);
        }
        float ma = s1a * (1.0f / HID);
        float va = (s2a - (float)HID * ma * ma) * (1.0f / (HID - 1));
        float ia = SCALE / (sqrtf(va) + 1e-6f);
        float mb = s1b * (1.0f / HID);
        float vb = (s2b - (float)HID * mb * mb) * (1.0f / (HID - 1));
        float ib = SCALE / (sqrtf(vb) + 1e-6f);
#pragma unroll
        for (int nf = 0; nf < 8; ++nf) {
            int c0 = nf * 8 + qid * 2;
            *(float2*)&hs[r0 * HST + c0] =
                make_float2((acc[nf][0] - ma) * ia, (acc[nf][1] - ma) * ia);
            *(float2*)&hs[r1 * HST + c0] =
                make_float2((acc[nf][2] - mb) * ib, (acc[nf][3] - mb) * ib);
        }
    }
    __syncthreads();

    // stage layer-2 coefficients (16KB resident)
    {
        const uint4* src = (const uint4*)g_w2;
        uint4* dst = (uint4*)(smc + SM_W);
#pragma unroll
        for (int j = 0; j < 4; ++j) dst[t + j * 256] = src[t + j * 256];
    }
    __syncthreads();

    // ---- layer 2: K = 64 x 16, 1 n-frag, 2 MMAs per i ---------------------
    float acc2[4] = {0.f, 0.f, 0.f, 0.f};
    for (int i = 0; i < NI2; ++i) {
        float x0 = hs[r0 * HST + i];
        float x1 = hs[r1 * HST + i];
        uint32_t ah[4], al[4];
        build_a(x0, x1, cc, ah, al);
        uint2 v = Wb[i * 32 + lane];
        mma16816(acc2, ah, v.x, v.y);
        mma16816(acc2, al, v.x, v.y);
    }

    // ---- output: cols 0..4 of the n-frag ----------------------------------
    {
        float* op0 = out + (size_t)(row0 + r0) * OUTD;
        float* op1 = out + (size_t)(row0 + r1) * OUTD;
        if (qid < 2) {
            op0[qid * 2]     = acc2[0];
            op0[qid * 2 + 1] = acc2[1];
            op1[qid * 2]     = acc2[2];
            op1[qid * 2 + 1] = acc2[3];
        } else if (qid == 2) {
            op0[4] = acc2[0];
            op1[4] = acc2[2];
        }
    }
}

// ---------------------------------------------------------------------------
extern "C" void kernel_launch(void* const* d_in, const int* in_sizes, int n_in,
                              void* d_out, int out_size) {
    (void)in_sizes; (void)n_in; (void)out_size;
    const float* x       = (const float*)d_in[0];
    const float* c1      = (const float*)d_in[1];
    const float* c2      = (const float*)d_in[2];
    const float* centers = (const float*)d_in[3];
    float* out = (float*)d_out;

    cudaFuncSetAttribute(kan_main, cudaFuncAttributeMaxDynamicSharedMemorySize, SM_TOTAL);

    kan_prep<<<(NI1 * 8 * 32 + NTHR - 1) / NTHR, NTHR>>>(c1, c2);
    kan_main<<<BATCH / MTILE, NTHR, SM_TOTAL>>>(x, centers, out);
}